// round 14
// baseline (speedup 1.0000x reference)
#include <cuda_runtime.h>
#include <cuda_fp16.h>
#include <cstdint>

#define NE   8
#define NT   4096
#define NDIN 2048
#define NDH  1408

// ---- fp16 scratch ----
__device__ __align__(16) __half g_xh[(size_t)NE * NT * NDIN];    // x fp16, row-major
__device__ __align__(16) __half g_gt[(size_t)NE * NDH * NDIN];   // gate^T  [E][N][K]
__device__ __align__(16) __half g_dt[(size_t)NE * NDH * NDIN];   // down^T  [E][N][K]
__device__ __align__(16) __half g_ut[(size_t)NE * NDIN * NDH];   // up^T    [E][N][K]
__device__ __align__(16) __half g_h [(size_t)NE * NT * NDH];     // silu(x@g)*(x@d)

__device__ __forceinline__ uint32_t smem_u32(const void* p) {
    uint32_t a;
    asm("{ .reg .u64 t; cvta.to.shared.u64 t, %1; cvt.u32.u64 %0, t; }" : "=r"(a) : "l"(p));
    return a;
}

#define CP16(dst, src) \
    asm volatile("cp.async.cg.shared.global [%0], [%1], 16;" :: "r"(dst), "l"(src))
#define CP_COMMIT() asm volatile("cp.async.commit_group;")
#define CP_WAITG(n) asm volatile("cp.async.wait_group %0;" :: "n"(n))

#define LDSM_X4(r, a) \
    asm volatile("ldmatrix.sync.aligned.m8n8.x4.shared.b16 {%0,%1,%2,%3}, [%4];" \
        : "=r"((r)[0]), "=r"((r)[1]), "=r"((r)[2]), "=r"((r)[3]) : "r"(a))
#define LDSM_X2(r, a) \
    asm volatile("ldmatrix.sync.aligned.m8n8.x2.shared.b16 {%0,%1}, [%2];" \
        : "=r"((r)[0]), "=r"((r)[1]) : "r"(a))

#define HMMA(c, a, b) \
    asm volatile("mma.sync.aligned.m16n8k16.row.col.f32.f16.f16.f32 " \
        "{%0,%1,%2,%3},{%4,%5,%6,%7},{%8,%9},{%0,%1,%2,%3};" \
        : "+f"((c)[0]), "+f"((c)[1]), "+f"((c)[2]), "+f"((c)[3]) \
        : "r"((a)[0]), "r"((a)[1]), "r"((a)[2]), "r"((a)[3]), "r"((b)[0]), "r"((b)[1]))

__device__ __forceinline__ float silu(float x) { return x / (1.0f + __expf(-x)); }

// ---------------- pre-pass: x -> fp16 ----------------
__global__ void __launch_bounds__(256) cvt_x(const float4* __restrict__ x, uint2* __restrict__ o) {
    size_t i = (size_t)blockIdx.x * 256 + threadIdx.x;
    float4 v = x[i];
    __half2 a = __floats2half2_rn(v.x, v.y);
    __half2 b = __floats2half2_rn(v.z, v.w);
    uint2 r;
    r.x = *(uint32_t*)&a;
    r.y = *(uint32_t*)&b;
    o[i] = r;
}

// ---------------- pre-pass: W [E][K][N] fp32 -> Wt [E][N][K] fp16 ----------------
__global__ void __launch_bounds__(256) tr_w(const float* __restrict__ W, __half* __restrict__ Wt,
                                            int K, int N) {
    __shared__ float s[64][65];
    const int e = blockIdx.z;
    const int n0 = blockIdx.x * 64;
    const int k0 = blockIdx.y * 64;
    const float* We = W + (size_t)e * K * N;
    __half* Wte = Wt + (size_t)e * K * N;
    const int tx = threadIdx.x & 63, ty = threadIdx.x >> 6;
    #pragma unroll
    for (int r = 0; r < 16; r++)
        s[ty * 16 + r][tx] = We[(size_t)(k0 + ty * 16 + r) * N + n0 + tx];
    __syncthreads();
    #pragma unroll
    for (int r = 0; r < 16; r++)
        Wte[(size_t)(n0 + ty * 16 + r) * K + k0 + tx] = __float2half_rn(s[tx][ty * 16 + r]);
}

// ---------------- fused GEMM1+2: h = silu(x@gate^T) * (x@down^T) ----------------
// BM=BN=128, BK=64, 4-stage (48KB each), single-barrier pipeline.
// 512 threads = 16 warps (4m x 4n), warp tile 32x32, dual accumulators.
__global__ void __launch_bounds__(512, 1)
gemm_fused(const __half* __restrict__ A, const __half* __restrict__ Bg,
           const __half* __restrict__ Bd, __half* __restrict__ H, int N, int K)
{
    extern __shared__ char sm[];
    const uint32_t sbase = smem_u32(sm);
    const int NK = K >> 6;                 // 32
    const int e = blockIdx.z, bm = blockIdx.y * 128, bn = blockIdx.x * 128;
    const int tid = threadIdx.x, lane = tid & 31, wid = tid >> 5;

    const char* Ae  = (const char*)(A  + ((size_t)e * NT + bm) * K);
    const char* Bge = (const char*)(Bg + ((size_t)e * N  + bn) * K);
    const char* Bde = (const char*)(Bd + ((size_t)e * N  + bn) * K);
    const size_t rowstride = (size_t)K * 2;

    auto stage_load = [&](int kc, int s) {
        if (kc < NK) {
            const uint32_t d = sbase + (uint32_t)s * 49152u;
            const char* pa = Ae  + (size_t)kc * 128;
            const char* pg = Bge + (size_t)kc * 128;
            const char* pd = Bde + (size_t)kc * 128;
            #pragma unroll
            for (int i = 0; i < 2; i++) {
                const int r = i * 64 + (tid >> 3);
                const int c = tid & 7;
                const uint32_t sw = (uint32_t)r * 128 + (uint32_t)((c ^ (r & 7)) << 4);
                const size_t go = (size_t)r * rowstride + c * 16;
                CP16(d + sw,          pa + go);
                CP16(d + 16384u + sw, pg + go);
                CP16(d + 32768u + sw, pd + go);
            }
        }
        CP_COMMIT();
    };

    stage_load(0, 0);
    stage_load(1, 1);
    stage_load(2, 2);

    const int wm = (wid >> 2) * 32;
    const int wn = (wid & 3) * 32;
    const int grp = lane >> 2, tig = lane & 3;
    const int hiA = lane >> 4;
    const int hiB = (lane >> 3) & 1;
    const int s7  = lane & 7;
    const int nrow = (lane & 7) + ((lane >> 4) << 3);   // B x4 row pattern

    float ag[2][4][4], ad_[2][4][4];
    #pragma unroll
    for (int i = 0; i < 2; i++)
        #pragma unroll
        for (int j = 0; j < 4; j++)
            #pragma unroll
            for (int q = 0; q < 4; q++) { ag[i][j][q] = 0.0f; ad_[i][j][q] = 0.0f; }

    for (int kc = 0; kc < NK; kc++) {
        const int s = kc & 3;
        CP_WAITG(2);
        __syncthreads();

        const uint32_t sA  = sbase + (uint32_t)s * 49152u;
        const uint32_t aBase  = sA + (uint32_t)(wm + (lane & 15)) * 128;
        const uint32_t bgBase = sA + 16384u + (uint32_t)(wn + nrow) * 128;
        const uint32_t bdBase = sA + 32768u + (uint32_t)(wn + nrow) * 128;

        // ks=0 fragment loads first (critical path), then refill, then HMMA
        uint32_t af0[2][4], bg0[2][4], bd0[2][4];
        {
            const uint32_t ca = (uint32_t)((hiA ^ s7) << 4);
            const uint32_t cb = (uint32_t)((hiB ^ s7) << 4);
            #pragma unroll
            for (int mt = 0; mt < 2; mt++)
                LDSM_X4(af0[mt], aBase + (uint32_t)mt * 2048 + ca);
            #pragma unroll
            for (int n4 = 0; n4 < 2; n4++) {
                LDSM_X4(bg0[n4], bgBase + (uint32_t)n4 * 2048 + cb);
                LDSM_X4(bd0[n4], bdBase + (uint32_t)n4 * 2048 + cb);
            }
        }

        stage_load(kc + 3, (kc + 3) & 3);

        #pragma unroll
        for (int mt = 0; mt < 2; mt++)
            #pragma unroll
            for (int nt = 0; nt < 4; nt++) {
                HMMA(ag[mt][nt],  af0[mt], &bg0[nt >> 1][(nt & 1) * 2]);
                HMMA(ad_[mt][nt], af0[mt], &bd0[nt >> 1][(nt & 1) * 2]);
            }

        #pragma unroll
        for (int ks = 1; ks < 4; ks++) {
            uint32_t af[2][4], bg[2][4], bd[2][4];
            const uint32_t ca = (uint32_t)(((ks * 2 + hiA) ^ s7) << 4);
            const uint32_t cb = (uint32_t)(((ks * 2 + hiB) ^ s7) << 4);
            #pragma unroll
            for (int mt = 0; mt < 2; mt++)
                LDSM_X4(af[mt], aBase + (uint32_t)mt * 2048 + ca);
            #pragma unroll
            for (int n4 = 0; n4 < 2; n4++) {
                LDSM_X4(bg[n4], bgBase + (uint32_t)n4 * 2048 + cb);
                LDSM_X4(bd[n4], bdBase + (uint32_t)n4 * 2048 + cb);
            }
            #pragma unroll
            for (int mt = 0; mt < 2; mt++)
                #pragma unroll
                for (int nt = 0; nt < 4; nt++) {
                    HMMA(ag[mt][nt],  af[mt], &bg[nt >> 1][(nt & 1) * 2]);
                    HMMA(ad_[mt][nt], af[mt], &bd[nt >> 1][(nt & 1) * 2]);
                }
        }
    }

    // epilogue: h = silu(g) * d, fp16
    #pragma unroll
    for (int mt = 0; mt < 2; mt++) {
        #pragma unroll
        for (int nt = 0; nt < 4; nt++) {
            const int row0 = bm + wm + mt * 16 + grp;
            const int col0 = bn + wn + nt * 8 + tig * 2;
            float h0 = silu(ag[mt][nt][0]) * ad_[mt][nt][0];
            float h1 = silu(ag[mt][nt][1]) * ad_[mt][nt][1];
            float h2 = silu(ag[mt][nt][2]) * ad_[mt][nt][2];
            float h3 = silu(ag[mt][nt][3]) * ad_[mt][nt][3];
            __half* out = H + ((size_t)e * NT + row0) * N + col0;
            *(__half2*)out = __floats2half2_rn(h0, h1);
            *(__half2*)(out + (size_t)8 * N) = __floats2half2_rn(h2, h3);
        }
    }
}

// ---------------- GEMM3: out = h @ up^T (fp32 out) ----------------
// BM=BN=128, BK=64, 3-stage (prefetch 2, waitg 1), single barrier.
// 512 threads = 16 warps (4m x 4n), warp tile 32x32.
__global__ void __launch_bounds__(512, 1)
gemm_hmma(const __half* __restrict__ A, const __half* __restrict__ Bt,
          float* __restrict__ Cout, int N, int K)
{
    extern __shared__ char sm[];
    const uint32_t sbase = smem_u32(sm);
    const int NK = K >> 6;
    const int e = blockIdx.z, bm = blockIdx.y * 128, bn = blockIdx.x * 128;
    const int tid = threadIdx.x, lane = tid & 31, wid = tid >> 5;

    const char* Ae = (const char*)(A  + ((size_t)e * NT + bm) * K);
    const char* Be = (const char*)(Bt + ((size_t)e * N  + bn) * K);
    const size_t rowstride = (size_t)K * 2;

    auto stage_load = [&](int kc, int s) {
        if (kc < NK) {
            const uint32_t dA = sbase + s * 32768u;
            const uint32_t dB = dA + 16384u;
            const char* pa = Ae + (size_t)kc * 128;
            const char* pb = Be + (size_t)kc * 128;
            // 512 threads: 64 rows x 8 chunks per pass, 2 passes per array
            #pragma unroll
            for (int i = 0; i < 2; i++) {
                const int r = i * 64 + (tid >> 3);
                const int c = tid & 7;
                const uint32_t sw = (uint32_t)r * 128 + (uint32_t)((c ^ (r & 7)) << 4);
                const size_t go = (size_t)r * rowstride + c * 16;
                CP16(dA + sw, pa + go);
                CP16(dB + sw, pb + go);
            }
        }
        CP_COMMIT();
    };

    stage_load(0, 0);
    stage_load(1, 1);

    const int wm = (wid >> 2) * 32;
    const int wn = (wid & 3) * 32;
    const int grp = lane >> 2, tig = lane & 3;
    const int hiA = lane >> 4;
    const int hiB = (lane >> 3) & 1;
    const int s7  = lane & 7;
    const int nrow = (lane & 7) + ((lane >> 4) << 3);

    float acc[2][4][4];
    #pragma unroll
    for (int i = 0; i < 2; i++)
        #pragma unroll
        for (int j = 0; j < 4; j++)
            #pragma unroll
            for (int q = 0; q < 4; q++)
                acc[i][j][q] = 0.0f;

    for (int kc = 0; kc < NK; kc++) {
        const int s = kc % 3;
        CP_WAITG(1);
        __syncthreads();

        const uint32_t sA = sbase + s * 32768u;
        const uint32_t sB = sA + 16384u;
        const uint32_t aBase = sA + (uint32_t)(wm + (lane & 15)) * 128;
        const uint32_t bBase = sB + (uint32_t)(wn + nrow) * 128;

        uint32_t af0[2][4], bf0[2][4];
        {
            const uint32_t ca = (uint32_t)((hiA ^ s7) << 4);
            const uint32_t cb = (uint32_t)((hiB ^ s7) << 4);
            #pragma unroll
            for (int mt = 0; mt < 2; mt++)
                LDSM_X4(af0[mt], aBase + (uint32_t)mt * 2048 + ca);
            #pragma unroll
            for (int n4 = 0; n4 < 2; n4++)
                LDSM_X4(bf0[n4], bBase + (uint32_t)n4 * 2048 + cb);
        }

        stage_load(kc + 2, (kc + 2) % 3);

        #pragma unroll
        for (int mt = 0; mt < 2; mt++)
            #pragma unroll
            for (int nt = 0; nt < 4; nt++)
                HMMA(acc[mt][nt], af0[mt], &bf0[nt >> 1][(nt & 1) * 2]);

        #pragma unroll
        for (int ks = 1; ks < 4; ks++) {
            uint32_t af[2][4], bf[2][4];
            const uint32_t ca = (uint32_t)(((ks * 2 + hiA) ^ s7) << 4);
            const uint32_t cb = (uint32_t)(((ks * 2 + hiB) ^ s7) << 4);
            #pragma unroll
            for (int mt = 0; mt < 2; mt++)
                LDSM_X4(af[mt], aBase + (uint32_t)mt * 2048 + ca);
            #pragma unroll
            for (int n4 = 0; n4 < 2; n4++)
                LDSM_X4(bf[n4], bBase + (uint32_t)n4 * 2048 + cb);
            #pragma unroll
            for (int mt = 0; mt < 2; mt++)
                #pragma unroll
                for (int nt = 0; nt < 4; nt++)
                    HMMA(acc[mt][nt], af[mt], &bf[nt >> 1][(nt & 1) * 2]);
        }
    }

    #pragma unroll
    for (int mt = 0; mt < 2; mt++) {
        #pragma unroll
        for (int nt = 0; nt < 4; nt++) {
            const int row0 = bm + wm + mt * 16 + grp;
            const int col0 = bn + wn + nt * 8 + tig * 2;
            float* out = Cout + ((size_t)e * NT + row0) * N + col0;
            *(float2*)out = make_float2(acc[mt][nt][0], acc[mt][nt][1]);
            *(float2*)(out + (size_t)8 * N) = make_float2(acc[mt][nt][2], acc[mt][nt][3]);
        }
    }
}

// ---------------- host ----------------
extern "C" void kernel_launch(void* const* d_in, const int* in_sizes, int n_in,
                              void* d_out, int out_size) {
    const float* x    = (const float*)d_in[0];
    const float* gate = (const float*)d_in[1];
    const float* down = (const float*)d_in[2];
    const float* up   = (const float*)d_in[3];
    float* out = (float*)d_out;

    void *xh, *gt, *dt, *ut, *hp;
    cudaGetSymbolAddress(&xh, g_xh);
    cudaGetSymbolAddress(&gt, g_gt);
    cudaGetSymbolAddress(&dt, g_dt);
    cudaGetSymbolAddress(&ut, g_ut);
    cudaGetSymbolAddress(&hp, g_h);

    const int SMEM_F = 4 * 49152;   // 192 KB
    const int SMEM_3 = 3 * 32768;   // 96 KB
    cudaFuncSetAttribute(gemm_fused, cudaFuncAttributeMaxDynamicSharedMemorySize, SMEM_F);
    cudaFuncSetAttribute(gemm_hmma,  cudaFuncAttributeMaxDynamicSharedMemorySize, SMEM_3);

    // pre-passes (separate kernels — R12 structure; up^T between the GEMMs)
    cvt_x<<<(NE * NT * NDIN / 4) / 256, 256>>>((const float4*)x, (uint2*)xh);
    tr_w<<<dim3(NDH / 64, NDIN / 64, NE), 256>>>(gate, (__half*)gt, NDIN, NDH);
    tr_w<<<dim3(NDH / 64, NDIN / 64, NE), 256>>>(down, (__half*)dt, NDIN, NDH);

    // fused: h = silu(x@gate^T) * (x@down^T)
    gemm_fused<<<dim3(NDH / 128, NT / 128, NE), 512, SMEM_F>>>(
        (const __half*)xh, (const __half*)gt, (const __half*)dt, (__half*)hp, NDH, NDIN);

    tr_w<<<dim3(NDIN / 64, NDH / 64, NE), 256>>>(up, (__half*)ut, NDH, NDIN);

    // out = h @ up^T
    gemm_hmma<<<dim3(NDIN / 128, NT / 128, NE), 512, SMEM_3>>>(
        (const __half*)hp, (const __half*)ut, out, NDIN, NDH);
}

// round 15
// speedup vs baseline: 1.0695x; 1.0695x over previous
#include <cuda_runtime.h>
#include <cuda_fp16.h>
#include <cstdint>

#define NE   8
#define NT   4096
#define NDIN 2048
#define NDH  1408

// ---- fp16 scratch ----
__device__ __align__(16) __half g_xh[(size_t)NE * NT * NDIN];    // x fp16, row-major
__device__ __align__(16) __half g_gt[(size_t)NE * NDH * NDIN];   // gate^T  [E][N][K]
__device__ __align__(16) __half g_dt[(size_t)NE * NDH * NDIN];   // down^T  [E][N][K]
__device__ __align__(16) __half g_ut[(size_t)NE * NDIN * NDH];   // up^T    [E][N][K]
__device__ __align__(16) __half g_h [(size_t)NE * NT * NDH];     // silu(x@g)*(x@d)

__device__ __forceinline__ uint32_t smem_u32(const void* p) {
    uint32_t a;
    asm("{ .reg .u64 t; cvta.to.shared.u64 t, %1; cvt.u32.u64 %0, t; }" : "=r"(a) : "l"(p));
    return a;
}

#define CP16(dst, src) \
    asm volatile("cp.async.cg.shared.global [%0], [%1], 16;" :: "r"(dst), "l"(src))
#define CP_COMMIT() asm volatile("cp.async.commit_group;")
#define CP_WAITG(n) asm volatile("cp.async.wait_group %0;" :: "n"(n))

#define LDSM_X4(r, a) \
    asm volatile("ldmatrix.sync.aligned.m8n8.x4.shared.b16 {%0,%1,%2,%3}, [%4];" \
        : "=r"((r)[0]), "=r"((r)[1]), "=r"((r)[2]), "=r"((r)[3]) : "r"(a))
#define LDSM_X2(r, a) \
    asm volatile("ldmatrix.sync.aligned.m8n8.x2.shared.b16 {%0,%1}, [%2];" \
        : "=r"((r)[0]), "=r"((r)[1]) : "r"(a))

#define HMMA(c, a, b) \
    asm volatile("mma.sync.aligned.m16n8k16.row.col.f32.f16.f16.f32 " \
        "{%0,%1,%2,%3},{%4,%5,%6,%7},{%8,%9},{%0,%1,%2,%3};" \
        : "+f"((c)[0]), "+f"((c)[1]), "+f"((c)[2]), "+f"((c)[3]) \
        : "r"((a)[0]), "r"((a)[1]), "r"((a)[2]), "r"((a)[3]), "r"((b)[0]), "r"((b)[1]))

__device__ __forceinline__ float silu(float x) { return x / (1.0f + __expf(-x)); }

// ---------------- pre-pass: x -> fp16 ----------------
__global__ void __launch_bounds__(256) cvt_x(const float4* __restrict__ x, uint2* __restrict__ o) {
    size_t i = (size_t)blockIdx.x * 256 + threadIdx.x;
    float4 v = x[i];
    __half2 a = __floats2half2_rn(v.x, v.y);
    __half2 b = __floats2half2_rn(v.z, v.w);
    uint2 r;
    r.x = *(uint32_t*)&a;
    r.y = *(uint32_t*)&b;
    o[i] = r;
}

// ---------------- pre-pass: W [E][K][N] fp32 -> Wt [E][N][K] fp16 ----------------
__device__ __forceinline__ void tr_w_body(const float* __restrict__ W, __half* __restrict__ Wt,
                                          int K, int N, int e) {
    __shared__ float s[64][65];
    const int n0 = blockIdx.x * 64;
    const int k0 = blockIdx.y * 64;
    const float* We = W + (size_t)e * K * N;
    __half* Wte = Wt + (size_t)e * K * N;
    const int tx = threadIdx.x & 63, ty = threadIdx.x >> 6;
    #pragma unroll
    for (int r = 0; r < 16; r++)
        s[ty * 16 + r][tx] = We[(size_t)(k0 + ty * 16 + r) * N + n0 + tx];
    __syncthreads();
    #pragma unroll
    for (int r = 0; r < 16; r++)
        Wte[(size_t)(n0 + ty * 16 + r) * K + k0 + tx] = __float2half_rn(s[tx][ty * 16 + r]);
}

__global__ void __launch_bounds__(256) tr_w(const float* __restrict__ W, __half* __restrict__ Wt,
                                            int K, int N) {
    tr_w_body(W, Wt, K, N, blockIdx.z);
}

// batched gate+down transpose: z in [0,16) -> gate for z<8, down for z>=8
__global__ void __launch_bounds__(256) tr_w_gd(const float* __restrict__ gate,
                                               const float* __restrict__ down) {
    const int z = blockIdx.z;
    if (z < NE) tr_w_body(gate, g_gt, NDIN, NDH, z);
    else        tr_w_body(down, g_dt, NDIN, NDH, z - NE);
}

// ---------------- fused GEMM1+2: h = silu(x@gate^T) * (x@down^T) ----------------
// BM=BN=128, BK=64, 4-stage (48KB each), single-barrier pipeline.
// 512 threads = 16 warps (4m x 4n), warp tile 32x32, dual accumulators.
__global__ void __launch_bounds__(512, 1)
gemm_fused(const __half* __restrict__ A, const __half* __restrict__ Bg,
           const __half* __restrict__ Bd, __half* __restrict__ H, int N, int K)
{
    extern __shared__ char sm[];
    const uint32_t sbase = smem_u32(sm);
    const int NK = K >> 6;                 // 32
    const int e = blockIdx.z, bm = blockIdx.y * 128, bn = blockIdx.x * 128;
    const int tid = threadIdx.x, lane = tid & 31, wid = tid >> 5;

    const char* Ae  = (const char*)(A  + ((size_t)e * NT + bm) * K);
    const char* Bge = (const char*)(Bg + ((size_t)e * N  + bn) * K);
    const char* Bde = (const char*)(Bd + ((size_t)e * N  + bn) * K);
    const size_t rowstride = (size_t)K * 2;

    auto stage_load = [&](int kc, int s) {
        if (kc < NK) {
            const uint32_t d = sbase + (uint32_t)s * 49152u;
            const char* pa = Ae  + (size_t)kc * 128;
            const char* pg = Bge + (size_t)kc * 128;
            const char* pd = Bde + (size_t)kc * 128;
            #pragma unroll
            for (int i = 0; i < 2; i++) {
                const int r = i * 64 + (tid >> 3);
                const int c = tid & 7;
                const uint32_t sw = (uint32_t)r * 128 + (uint32_t)((c ^ (r & 7)) << 4);
                const size_t go = (size_t)r * rowstride + c * 16;
                CP16(d + sw,          pa + go);
                CP16(d + 16384u + sw, pg + go);
                CP16(d + 32768u + sw, pd + go);
            }
        }
        CP_COMMIT();
    };

    stage_load(0, 0);
    stage_load(1, 1);
    stage_load(2, 2);

    const int wm = (wid >> 2) * 32;
    const int wn = (wid & 3) * 32;
    const int grp = lane >> 2, tig = lane & 3;
    const int hiA = lane >> 4;
    const int hiB = (lane >> 3) & 1;
    const int s7  = lane & 7;
    const int nrow = (lane & 7) + ((lane >> 4) << 3);   // B x4 row pattern

    float ag[2][4][4], ad_[2][4][4];
    #pragma unroll
    for (int i = 0; i < 2; i++)
        #pragma unroll
        for (int j = 0; j < 4; j++)
            #pragma unroll
            for (int q = 0; q < 4; q++) { ag[i][j][q] = 0.0f; ad_[i][j][q] = 0.0f; }

    for (int kc = 0; kc < NK; kc++) {
        const int s = kc & 3;
        CP_WAITG(2);
        __syncthreads();

        const uint32_t sA  = sbase + (uint32_t)s * 49152u;
        const uint32_t aBase  = sA + (uint32_t)(wm + (lane & 15)) * 128;
        const uint32_t bgBase = sA + 16384u + (uint32_t)(wn + nrow) * 128;
        const uint32_t bdBase = sA + 32768u + (uint32_t)(wn + nrow) * 128;

        // ks=0 fragment loads first (critical path), then refill, then HMMA
        uint32_t af0[2][4], bg0[2][4], bd0[2][4];
        {
            const uint32_t ca = (uint32_t)((hiA ^ s7) << 4);
            const uint32_t cb = (uint32_t)((hiB ^ s7) << 4);
            #pragma unroll
            for (int mt = 0; mt < 2; mt++)
                LDSM_X4(af0[mt], aBase + (uint32_t)mt * 2048 + ca);
            #pragma unroll
            for (int n4 = 0; n4 < 2; n4++) {
                LDSM_X4(bg0[n4], bgBase + (uint32_t)n4 * 2048 + cb);
                LDSM_X4(bd0[n4], bdBase + (uint32_t)n4 * 2048 + cb);
            }
        }

        stage_load(kc + 3, (kc + 3) & 3);

        #pragma unroll
        for (int mt = 0; mt < 2; mt++)
            #pragma unroll
            for (int nt = 0; nt < 4; nt++) {
                HMMA(ag[mt][nt],  af0[mt], &bg0[nt >> 1][(nt & 1) * 2]);
                HMMA(ad_[mt][nt], af0[mt], &bd0[nt >> 1][(nt & 1) * 2]);
            }

        #pragma unroll
        for (int ks = 1; ks < 4; ks++) {
            uint32_t af[2][4], bg[2][4], bd[2][4];
            const uint32_t ca = (uint32_t)(((ks * 2 + hiA) ^ s7) << 4);
            const uint32_t cb = (uint32_t)(((ks * 2 + hiB) ^ s7) << 4);
            #pragma unroll
            for (int mt = 0; mt < 2; mt++)
                LDSM_X4(af[mt], aBase + (uint32_t)mt * 2048 + ca);
            #pragma unroll
            for (int n4 = 0; n4 < 2; n4++) {
                LDSM_X4(bg[n4], bgBase + (uint32_t)n4 * 2048 + cb);
                LDSM_X4(bd[n4], bdBase + (uint32_t)n4 * 2048 + cb);
            }
            #pragma unroll
            for (int mt = 0; mt < 2; mt++)
                #pragma unroll
                for (int nt = 0; nt < 4; nt++) {
                    HMMA(ag[mt][nt],  af[mt], &bg[nt >> 1][(nt & 1) * 2]);
                    HMMA(ad_[mt][nt], af[mt], &bd[nt >> 1][(nt & 1) * 2]);
                }
        }
    }

    // epilogue: h = silu(g) * d, fp16
    #pragma unroll
    for (int mt = 0; mt < 2; mt++) {
        #pragma unroll
        for (int nt = 0; nt < 4; nt++) {
            const int row0 = bm + wm + mt * 16 + grp;
            const int col0 = bn + wn + nt * 8 + tig * 2;
            float h0 = silu(ag[mt][nt][0]) * ad_[mt][nt][0];
            float h1 = silu(ag[mt][nt][1]) * ad_[mt][nt][1];
            float h2 = silu(ag[mt][nt][2]) * ad_[mt][nt][2];
            float h3 = silu(ag[mt][nt][3]) * ad_[mt][nt][3];
            __half* out = H + ((size_t)e * NT + row0) * N + col0;
            *(__half2*)out = __floats2half2_rn(h0, h1);
            *(__half2*)(out + (size_t)8 * N) = __floats2half2_rn(h2, h3);
        }
    }
}

// ---------------- GEMM3: out = h @ up^T (fp32 out) ----------------
// R12 config: BM=BN=128, BK=64, 3-stage (prefetch 2, waitg 1), single barrier,
// 256 threads = 8 warps (2m x 4n), warp tile 64x32, 2 CTA/SM.
__global__ void __launch_bounds__(256, 2)
gemm_hmma(const __half* __restrict__ A, const __half* __restrict__ Bt,
          float* __restrict__ Cout, int N, int K)
{
    extern __shared__ char sm[];
    const uint32_t sbase = smem_u32(sm);
    const int NK = K >> 6;
    const int e = blockIdx.z, bm = blockIdx.y * 128, bn = blockIdx.x * 128;
    const int tid = threadIdx.x, lane = tid & 31, wid = tid >> 5;

    const char* Ae = (const char*)(A  + ((size_t)e * NT + bm) * K);
    const char* Be = (const char*)(Bt + ((size_t)e * N  + bn) * K);
    const size_t rowstride = (size_t)K * 2;

    auto stage_load = [&](int kc, int s) {
        if (kc < NK) {
            const uint32_t dA = sbase + s * 32768u;
            const uint32_t dB = dA + 16384u;
            const char* pa = Ae + (size_t)kc * 128;
            const char* pb = Be + (size_t)kc * 128;
            #pragma unroll
            for (int i = 0; i < 4; i++) {
                const int r = i * 32 + (tid >> 3);
                const int c = tid & 7;
                const uint32_t sw = (uint32_t)r * 128 + (uint32_t)((c ^ (r & 7)) << 4);
                const size_t go = (size_t)r * rowstride + c * 16;
                CP16(dA + sw, pa + go);
                CP16(dB + sw, pb + go);
            }
        }
        CP_COMMIT();
    };

    stage_load(0, 0);
    stage_load(1, 1);

    const int wm = (wid >> 2) * 64;
    const int wn = (wid & 3) * 32;
    const int grp = lane >> 2, tig = lane & 3;
    const int hiA = lane >> 4;
    const int hiB = (lane >> 3) & 1;
    const int s7  = lane & 7;

    float acc[4][4][4];
    #pragma unroll
    for (int i = 0; i < 4; i++)
        #pragma unroll
        for (int j = 0; j < 4; j++)
            #pragma unroll
            for (int q = 0; q < 4; q++)
                acc[i][j][q] = 0.0f;

    for (int kc = 0; kc < NK; kc++) {
        const int s = kc % 3;
        CP_WAITG(1);
        __syncthreads();
        // refill stage consumed last iteration
        stage_load(kc + 2, (kc + 2) % 3);

        const uint32_t sA = sbase + s * 32768u;
        const uint32_t sB = sA + 16384u;
        const uint32_t aBase = sA + (uint32_t)(wm + (lane & 15)) * 128;
        const uint32_t bBase = sB + (uint32_t)(wn + (lane & 7)) * 128;

        #pragma unroll
        for (int ks = 0; ks < 4; ks++) {
            uint32_t af[4][4], bf[4][2];
            const uint32_t ca = (uint32_t)(((ks * 2 + hiA) ^ s7) << 4);
            const uint32_t cb = (uint32_t)(((ks * 2 + hiB) ^ s7) << 4);
            #pragma unroll
            for (int mt = 0; mt < 4; mt++)
                LDSM_X4(af[mt], aBase + (uint32_t)mt * 2048 + ca);
            #pragma unroll
            for (int nt = 0; nt < 4; nt++)
                LDSM_X2(bf[nt], bBase + (uint32_t)nt * 1024 + cb);
            #pragma unroll
            for (int mt = 0; mt < 4; mt++)
                #pragma unroll
                for (int nt = 0; nt < 4; nt++)
                    HMMA(acc[mt][nt], af[mt], bf[nt]);
        }
    }

    #pragma unroll
    for (int mt = 0; mt < 4; mt++) {
        #pragma unroll
        for (int nt = 0; nt < 4; nt++) {
            const int row0 = bm + wm + mt * 16 + grp;
            const int col0 = bn + wn + nt * 8 + tig * 2;
            float* out = Cout + ((size_t)e * NT + row0) * N + col0;
            *(float2*)out = make_float2(acc[mt][nt][0], acc[mt][nt][1]);
            *(float2*)(out + (size_t)8 * N) = make_float2(acc[mt][nt][2], acc[mt][nt][3]);
        }
    }
}

// ---------------- host ----------------
extern "C" void kernel_launch(void* const* d_in, const int* in_sizes, int n_in,
                              void* d_out, int out_size) {
    const float* x    = (const float*)d_in[0];
    const float* gate = (const float*)d_in[1];
    const float* down = (const float*)d_in[2];
    const float* up   = (const float*)d_in[3];
    float* out = (float*)d_out;

    void *xh, *gt, *dt, *ut, *hp;
    cudaGetSymbolAddress(&xh, g_xh);
    cudaGetSymbolAddress(&gt, g_gt);
    cudaGetSymbolAddress(&dt, g_dt);
    cudaGetSymbolAddress(&ut, g_ut);
    cudaGetSymbolAddress(&hp, g_h);

    const int SMEM_F = 4 * 49152;   // 192 KB
    const int SMEM_3 = 3 * 32768;   // 96 KB
    cudaFuncSetAttribute(gemm_fused, cudaFuncAttributeMaxDynamicSharedMemorySize, SMEM_F);
    cudaFuncSetAttribute(gemm_hmma,  cudaFuncAttributeMaxDynamicSharedMemorySize, SMEM_3);

    // pre-passes
    cvt_x<<<(NE * NT * NDIN / 4) / 256, 256>>>((const float4*)x, (uint2*)xh);
    tr_w_gd<<<dim3(NDH / 64, NDIN / 64, 2 * NE), 256>>>(gate, down);

    // fused: h = silu(x@gate^T) * (x@down^T)
    gemm_fused<<<dim3(NDH / 128, NT / 128, NE), 512, SMEM_F>>>(
        (const __half*)xh, (const __half*)gt, (const __half*)dt, (__half*)hp, NDH, NDIN);

    tr_w<<<dim3(NDIN / 64, NDH / 64, NE), 256>>>(up, (__half*)ut, NDH, NDIN);

    // out = h @ up^T
    gemm_hmma<<<dim3(NDIN / 128, NT / 128, NE), 256, SMEM_3>>>(
        (const __half*)hp, (const __half*)ut, out, NDIN, NDH);
}

// round 16
// speedup vs baseline: 1.0749x; 1.0050x over previous
#include <cuda_runtime.h>
#include <cuda_fp16.h>
#include <cstdint>

#define NE   8
#define NT   4096
#define NDIN 2048
#define NDH  1408

// ---- fp16 scratch ----
__device__ __align__(16) __half g_xh[(size_t)NE * NT * NDIN];    // x fp16, row-major
__device__ __align__(16) __half g_gt[(size_t)NE * NDH * NDIN];   // gate^T  [E][N][K]
__device__ __align__(16) __half g_dt[(size_t)NE * NDH * NDIN];   // down^T  [E][N][K]
__device__ __align__(16) __half g_ut[(size_t)NE * NDIN * NDH];   // up^T    [E][N][K]
__device__ __align__(16) __half g_h [(size_t)NE * NT * NDH];     // silu(x@g)*(x@d)

__device__ __forceinline__ uint32_t smem_u32(const void* p) {
    uint32_t a;
    asm("{ .reg .u64 t; cvta.to.shared.u64 t, %1; cvt.u32.u64 %0, t; }" : "=r"(a) : "l"(p));
    return a;
}

#define CP16(dst, src) \
    asm volatile("cp.async.cg.shared.global [%0], [%1], 16;" :: "r"(dst), "l"(src))
#define CP_COMMIT() asm volatile("cp.async.commit_group;")
#define CP_WAITG(n) asm volatile("cp.async.wait_group %0;" :: "n"(n))

#define LDSM_X4(r, a) \
    asm volatile("ldmatrix.sync.aligned.m8n8.x4.shared.b16 {%0,%1,%2,%3}, [%4];" \
        : "=r"((r)[0]), "=r"((r)[1]), "=r"((r)[2]), "=r"((r)[3]) : "r"(a))
#define LDSM_X2(r, a) \
    asm volatile("ldmatrix.sync.aligned.m8n8.x2.shared.b16 {%0,%1}, [%2];" \
        : "=r"((r)[0]), "=r"((r)[1]) : "r"(a))

#define HMMA(c, a, b) \
    asm volatile("mma.sync.aligned.m16n8k16.row.col.f32.f16.f16.f32 " \
        "{%0,%1,%2,%3},{%4,%5,%6,%7},{%8,%9},{%0,%1,%2,%3};" \
        : "+f"((c)[0]), "+f"((c)[1]), "+f"((c)[2]), "+f"((c)[3]) \
        : "r"((a)[0]), "r"((a)[1]), "r"((a)[2]), "r"((a)[3]), "r"((b)[0]), "r"((b)[1]))

__device__ __forceinline__ float silu(float x) { return x / (1.0f + __expf(-x)); }

// ---------------- pre-pass: x -> fp16 ----------------
__global__ void __launch_bounds__(256) cvt_x(const float4* __restrict__ x, uint2* __restrict__ o) {
    size_t i = (size_t)blockIdx.x * 256 + threadIdx.x;
    float4 v = x[i];
    __half2 a = __floats2half2_rn(v.x, v.y);
    __half2 b = __floats2half2_rn(v.z, v.w);
    uint2 r;
    r.x = *(uint32_t*)&a;
    r.y = *(uint32_t*)&b;
    o[i] = r;
}

// ---------------- pre-pass: W [E][K][N] fp32 -> Wt [E][N][K] fp16 ----------------
__device__ __forceinline__ void tr_w_body(const float* __restrict__ W, __half* __restrict__ Wt,
                                          int K, int N, int e) {
    __shared__ float s[64][65];
    const int n0 = blockIdx.x * 64;
    const int k0 = blockIdx.y * 64;
    const float* We = W + (size_t)e * K * N;
    __half* Wte = Wt + (size_t)e * K * N;
    const int tx = threadIdx.x & 63, ty = threadIdx.x >> 6;
    #pragma unroll
    for (int r = 0; r < 16; r++)
        s[ty * 16 + r][tx] = We[(size_t)(k0 + ty * 16 + r) * N + n0 + tx];
    __syncthreads();
    #pragma unroll
    for (int r = 0; r < 16; r++)
        Wte[(size_t)(n0 + ty * 16 + r) * K + k0 + tx] = __float2half_rn(s[tx][ty * 16 + r]);
}

__global__ void __launch_bounds__(256) tr_w(const float* __restrict__ W, __half* __restrict__ Wt,
                                            int K, int N) {
    tr_w_body(W, Wt, K, N, blockIdx.z);
}

// batched gate+down transpose: z in [0,16) -> gate for z<8, down for z>=8
__global__ void __launch_bounds__(256) tr_w_gd(const float* __restrict__ gate,
                                               const float* __restrict__ down) {
    const int z = blockIdx.z;
    if (z < NE) tr_w_body(gate, g_gt, NDIN, NDH, z);
    else        tr_w_body(down, g_dt, NDIN, NDH, z - NE);
}

// ---------------- fused GEMM1+2: h = silu(x@gate^T) * (x@down^T) ----------------
// BM=BN=128, BK=64, 4-stage (48KB each), single-barrier pipeline.
// 512 threads = 16 warps (4m x 4n), warp tile 32x32, dual accumulators.
__global__ void __launch_bounds__(512, 1)
gemm_fused(const __half* __restrict__ A, const __half* __restrict__ Bg,
           const __half* __restrict__ Bd, __half* __restrict__ H, int N, int K)
{
    extern __shared__ char sm[];
    const uint32_t sbase = smem_u32(sm);
    const int NK = K >> 6;                 // 32
    const int e = blockIdx.z, bm = blockIdx.y * 128, bn = blockIdx.x * 128;
    const int tid = threadIdx.x, lane = tid & 31, wid = tid >> 5;

    const char* Ae  = (const char*)(A  + ((size_t)e * NT + bm) * K);
    const char* Bge = (const char*)(Bg + ((size_t)e * N  + bn) * K);
    const char* Bde = (const char*)(Bd + ((size_t)e * N  + bn) * K);
    const size_t rowstride = (size_t)K * 2;

    auto stage_load = [&](int kc, int s) {
        if (kc < NK) {
            const uint32_t d = sbase + (uint32_t)s * 49152u;
            const char* pa = Ae  + (size_t)kc * 128;
            const char* pg = Bge + (size_t)kc * 128;
            const char* pd = Bde + (size_t)kc * 128;
            #pragma unroll
            for (int i = 0; i < 2; i++) {
                const int r = i * 64 + (tid >> 3);
                const int c = tid & 7;
                const uint32_t sw = (uint32_t)r * 128 + (uint32_t)((c ^ (r & 7)) << 4);
                const size_t go = (size_t)r * rowstride + c * 16;
                CP16(d + sw,          pa + go);
                CP16(d + 16384u + sw, pg + go);
                CP16(d + 32768u + sw, pd + go);
            }
        }
        CP_COMMIT();
    };

    stage_load(0, 0);
    stage_load(1, 1);
    stage_load(2, 2);

    const int wm = (wid >> 2) * 32;
    const int wn = (wid & 3) * 32;
    const int grp = lane >> 2, tig = lane & 3;
    const int hiA = lane >> 4;
    const int hiB = (lane >> 3) & 1;
    const int s7  = lane & 7;
    const int nrow = (lane & 7) + ((lane >> 4) << 3);   // B x4 row pattern

    float ag[2][4][4], ad_[2][4][4];
    #pragma unroll
    for (int i = 0; i < 2; i++)
        #pragma unroll
        for (int j = 0; j < 4; j++)
            #pragma unroll
            for (int q = 0; q < 4; q++) { ag[i][j][q] = 0.0f; ad_[i][j][q] = 0.0f; }

    for (int kc = 0; kc < NK; kc++) {
        const int s = kc & 3;
        CP_WAITG(2);
        __syncthreads();

        const uint32_t sA  = sbase + (uint32_t)s * 49152u;
        const uint32_t aBase  = sA + (uint32_t)(wm + (lane & 15)) * 128;
        const uint32_t bgBase = sA + 16384u + (uint32_t)(wn + nrow) * 128;
        const uint32_t bdBase = sA + 32768u + (uint32_t)(wn + nrow) * 128;

        // ks=0 fragment loads first (critical path), then refill, then HMMA
        uint32_t af0[2][4], bg0[2][4], bd0[2][4];
        {
            const uint32_t ca = (uint32_t)((hiA ^ s7) << 4);
            const uint32_t cb = (uint32_t)((hiB ^ s7) << 4);
            #pragma unroll
            for (int mt = 0; mt < 2; mt++)
                LDSM_X4(af0[mt], aBase + (uint32_t)mt * 2048 + ca);
            #pragma unroll
            for (int n4 = 0; n4 < 2; n4++) {
                LDSM_X4(bg0[n4], bgBase + (uint32_t)n4 * 2048 + cb);
                LDSM_X4(bd0[n4], bdBase + (uint32_t)n4 * 2048 + cb);
            }
        }

        stage_load(kc + 3, (kc + 3) & 3);

        #pragma unroll
        for (int mt = 0; mt < 2; mt++)
            #pragma unroll
            for (int nt = 0; nt < 4; nt++) {
                HMMA(ag[mt][nt],  af0[mt], &bg0[nt >> 1][(nt & 1) * 2]);
                HMMA(ad_[mt][nt], af0[mt], &bd0[nt >> 1][(nt & 1) * 2]);
            }

        #pragma unroll
        for (int ks = 1; ks < 4; ks++) {
            uint32_t af[2][4], bg[2][4], bd[2][4];
            const uint32_t ca = (uint32_t)(((ks * 2 + hiA) ^ s7) << 4);
            const uint32_t cb = (uint32_t)(((ks * 2 + hiB) ^ s7) << 4);
            #pragma unroll
            for (int mt = 0; mt < 2; mt++)
                LDSM_X4(af[mt], aBase + (uint32_t)mt * 2048 + ca);
            #pragma unroll
            for (int n4 = 0; n4 < 2; n4++) {
                LDSM_X4(bg[n4], bgBase + (uint32_t)n4 * 2048 + cb);
                LDSM_X4(bd[n4], bdBase + (uint32_t)n4 * 2048 + cb);
            }
            #pragma unroll
            for (int mt = 0; mt < 2; mt++)
                #pragma unroll
                for (int nt = 0; nt < 4; nt++) {
                    HMMA(ag[mt][nt],  af[mt], &bg[nt >> 1][(nt & 1) * 2]);
                    HMMA(ad_[mt][nt], af[mt], &bd[nt >> 1][(nt & 1) * 2]);
                }
        }
    }

    // epilogue: h = silu(g) * d, fp16
    #pragma unroll
    for (int mt = 0; mt < 2; mt++) {
        #pragma unroll
        for (int nt = 0; nt < 4; nt++) {
            const int row0 = bm + wm + mt * 16 + grp;
            const int col0 = bn + wn + nt * 8 + tig * 2;
            float h0 = silu(ag[mt][nt][0]) * ad_[mt][nt][0];
            float h1 = silu(ag[mt][nt][1]) * ad_[mt][nt][1];
            float h2 = silu(ag[mt][nt][2]) * ad_[mt][nt][2];
            float h3 = silu(ag[mt][nt][3]) * ad_[mt][nt][3];
            __half* out = H + ((size_t)e * NT + row0) * N + col0;
            *(__half2*)out = __floats2half2_rn(h0, h1);
            *(__half2*)(out + (size_t)8 * N) = __floats2half2_rn(h2, h3);
        }
    }
}

// ---------------- GEMM3: out = h @ up^T (fp32 out) ----------------
// R12 config: BM=BN=128, BK=64, 3-stage (prefetch 2, waitg 1), single barrier,
// 256 threads = 8 warps (2m x 4n), warp tile 64x32, 2 CTA/SM.
__global__ void __launch_bounds__(256, 2)
gemm_hmma(const __half* __restrict__ A, const __half* __restrict__ Bt,
          float* __restrict__ Cout, int N, int K)
{
    extern __shared__ char sm[];
    const uint32_t sbase = smem_u32(sm);
    const int NK = K >> 6;
    const int e = blockIdx.z, bm = blockIdx.y * 128, bn = blockIdx.x * 128;
    const int tid = threadIdx.x, lane = tid & 31, wid = tid >> 5;

    const char* Ae = (const char*)(A  + ((size_t)e * NT + bm) * K);
    const char* Be = (const char*)(Bt + ((size_t)e * N  + bn) * K);
    const size_t rowstride = (size_t)K * 2;

    auto stage_load = [&](int kc, int s) {
        if (kc < NK) {
            const uint32_t dA = sbase + s * 32768u;
            const uint32_t dB = dA + 16384u;
            const char* pa = Ae + (size_t)kc * 128;
            const char* pb = Be + (size_t)kc * 128;
            #pragma unroll
            for (int i = 0; i < 4; i++) {
                const int r = i * 32 + (tid >> 3);
                const int c = tid & 7;
                const uint32_t sw = (uint32_t)r * 128 + (uint32_t)((c ^ (r & 7)) << 4);
                const size_t go = (size_t)r * rowstride + c * 16;
                CP16(dA + sw, pa + go);
                CP16(dB + sw, pb + go);
            }
        }
        CP_COMMIT();
    };

    stage_load(0, 0);
    stage_load(1, 1);

    const int wm = (wid >> 2) * 64;
    const int wn = (wid & 3) * 32;
    const int grp = lane >> 2, tig = lane & 3;
    const int hiA = lane >> 4;
    const int hiB = (lane >> 3) & 1;
    const int s7  = lane & 7;

    float acc[4][4][4];
    #pragma unroll
    for (int i = 0; i < 4; i++)
        #pragma unroll
        for (int j = 0; j < 4; j++)
            #pragma unroll
            for (int q = 0; q < 4; q++)
                acc[i][j][q] = 0.0f;

    for (int kc = 0; kc < NK; kc++) {
        const int s = kc % 3;
        CP_WAITG(1);
        __syncthreads();
        // refill stage consumed last iteration
        stage_load(kc + 2, (kc + 2) % 3);

        const uint32_t sA = sbase + s * 32768u;
        const uint32_t sB = sA + 16384u;
        const uint32_t aBase = sA + (uint32_t)(wm + (lane & 15)) * 128;
        const uint32_t bBase = sB + (uint32_t)(wn + (lane & 7)) * 128;

        #pragma unroll
        for (int ks = 0; ks < 4; ks++) {
            uint32_t af[4][4], bf[4][2];
            const uint32_t ca = (uint32_t)(((ks * 2 + hiA) ^ s7) << 4);
            const uint32_t cb = (uint32_t)(((ks * 2 + hiB) ^ s7) << 4);
            #pragma unroll
            for (int mt = 0; mt < 4; mt++)
                LDSM_X4(af[mt], aBase + (uint32_t)mt * 2048 + ca);
            #pragma unroll
            for (int nt = 0; nt < 4; nt++)
                LDSM_X2(bf[nt], bBase + (uint32_t)nt * 1024 + cb);
            #pragma unroll
            for (int mt = 0; mt < 4; mt++)
                #pragma unroll
                for (int nt = 0; nt < 4; nt++)
                    HMMA(acc[mt][nt], af[mt], bf[nt]);
        }
    }

    #pragma unroll
    for (int mt = 0; mt < 4; mt++) {
        #pragma unroll
        for (int nt = 0; nt < 4; nt++) {
            const int row0 = bm + wm + mt * 16 + grp;
            const int col0 = bn + wn + nt * 8 + tig * 2;
            float* out = Cout + ((size_t)e * NT + row0) * N + col0;
            *(float2*)out = make_float2(acc[mt][nt][0], acc[mt][nt][1]);
            *(float2*)(out + (size_t)8 * N) = make_float2(acc[mt][nt][2], acc[mt][nt][3]);
        }
    }
}

// ---------------- host ----------------
extern "C" void kernel_launch(void* const* d_in, const int* in_sizes, int n_in,
                              void* d_out, int out_size) {
    const float* x    = (const float*)d_in[0];
    const float* gate = (const float*)d_in[1];
    const float* down = (const float*)d_in[2];
    const float* up   = (const float*)d_in[3];
    float* out = (float*)d_out;

    void *xh, *gt, *dt, *ut, *hp;
    cudaGetSymbolAddress(&xh, g_xh);
    cudaGetSymbolAddress(&gt, g_gt);
    cudaGetSymbolAddress(&dt, g_dt);
    cudaGetSymbolAddress(&ut, g_ut);
    cudaGetSymbolAddress(&hp, g_h);

    const int SMEM_F = 4 * 49152;   // 192 KB
    const int SMEM_3 = 3 * 32768;   // 96 KB
    cudaFuncSetAttribute(gemm_fused, cudaFuncAttributeMaxDynamicSharedMemorySize, SMEM_F);
    cudaFuncSetAttribute(gemm_hmma,  cudaFuncAttributeMaxDynamicSharedMemorySize, SMEM_3);

    // fork/join: overlap weight transposes (side stream) with cvt_x and gemm_fused
    cudaStream_t side;
    cudaStreamCreateWithFlags(&side, cudaStreamNonBlocking);
    cudaEvent_t e0, e1, e2;
    cudaEventCreateWithFlags(&e0, cudaEventDisableTiming);
    cudaEventCreateWithFlags(&e1, cudaEventDisableTiming);
    cudaEventCreateWithFlags(&e2, cudaEventDisableTiming);

    // fork from the (capture) default stream
    cudaEventRecord(e0, 0);
    cudaStreamWaitEvent(side, e0, 0);

    // side stream: gate+down transpose, then up transpose
    tr_w_gd<<<dim3(NDH / 64, NDIN / 64, 2 * NE), 256, 0, side>>>(gate, down);
    cudaEventRecord(e1, side);
    tr_w<<<dim3(NDIN / 64, NDH / 64, NE), 256, 0, side>>>(up, (__half*)ut, NDH, NDIN);
    cudaEventRecord(e2, side);

    // main stream: x conversion (concurrent with tr_w_gd)
    cvt_x<<<(NE * NT * NDIN / 4) / 256, 256>>>((const float4*)x, (uint2*)xh);

    // fused needs gate^T/down^T
    cudaStreamWaitEvent(0, e1, 0);
    gemm_fused<<<dim3(NDH / 128, NT / 128, NE), 512, SMEM_F>>>(
        (const __half*)xh, (const __half*)gt, (const __half*)dt, (__half*)hp, NDH, NDIN);

    // GEMM3 needs up^T (tr_w(up) overlapped with gemm_fused)
    cudaStreamWaitEvent(0, e2, 0);
    gemm_hmma<<<dim3(NDIN / 128, NT / 128, NE), 256, SMEM_3>>>(
        (const __half*)hp, (const __half*)ut, out, NDIN, NDH);

    cudaEventDestroy(e0);
    cudaEventDestroy(e1);
    cudaEventDestroy(e2);
    cudaStreamDestroy(side);
}

// round 17
// speedup vs baseline: 1.1179x; 1.0399x over previous
#include <cuda_runtime.h>
#include <cuda_fp16.h>
#include <cstdint>

#define NE   8
#define NT   4096
#define NDIN 2048
#define NDH  1408

// ---- fp16 scratch ----
__device__ __align__(16) __half g_xh[(size_t)NE * NT * NDIN];    // x fp16, row-major
__device__ __align__(16) __half g_gt[(size_t)NE * NDH * NDIN];   // gate^T  [E][N][K]
__device__ __align__(16) __half g_dt[(size_t)NE * NDH * NDIN];   // down^T  [E][N][K]
__device__ __align__(16) __half g_ut[(size_t)NE * NDIN * NDH];   // up^T    [E][N][K]
__device__ __align__(16) __half g_h [(size_t)NE * NT * NDH];     // silu(x@g)*(x@d)

__device__ __forceinline__ uint32_t smem_u32(const void* p) {
    uint32_t a;
    asm("{ .reg .u64 t; cvta.to.shared.u64 t, %1; cvt.u32.u64 %0, t; }" : "=r"(a) : "l"(p));
    return a;
}

#define CP16(dst, src) \
    asm volatile("cp.async.cg.shared.global [%0], [%1], 16;" :: "r"(dst), "l"(src))
#define CP_COMMIT() asm volatile("cp.async.commit_group;")
#define CP_WAITG(n) asm volatile("cp.async.wait_group %0;" :: "n"(n))

#define LDSM_X4(r, a) \
    asm volatile("ldmatrix.sync.aligned.m8n8.x4.shared.b16 {%0,%1,%2,%3}, [%4];" \
        : "=r"((r)[0]), "=r"((r)[1]), "=r"((r)[2]), "=r"((r)[3]) : "r"(a))
#define LDSM_X2(r, a) \
    asm volatile("ldmatrix.sync.aligned.m8n8.x2.shared.b16 {%0,%1}, [%2];" \
        : "=r"((r)[0]), "=r"((r)[1]) : "r"(a))

#define HMMA(c, a, b) \
    asm volatile("mma.sync.aligned.m16n8k16.row.col.f32.f16.f16.f32 " \
        "{%0,%1,%2,%3},{%4,%5,%6,%7},{%8,%9},{%0,%1,%2,%3};" \
        : "+f"((c)[0]), "+f"((c)[1]), "+f"((c)[2]), "+f"((c)[3]) \
        : "r"((a)[0]), "r"((a)[1]), "r"((a)[2]), "r"((a)[3]), "r"((b)[0]), "r"((b)[1]))

__device__ __forceinline__ float silu(float x) { return x / (1.0f + __expf(-x)); }

// ---------------- pre-pass: x -> fp16 ----------------
__global__ void __launch_bounds__(256) cvt_x(const float4* __restrict__ x, uint2* __restrict__ o) {
    size_t i = (size_t)blockIdx.x * 256 + threadIdx.x;
    float4 v = x[i];
    __half2 a = __floats2half2_rn(v.x, v.y);
    __half2 b = __floats2half2_rn(v.z, v.w);
    uint2 r;
    r.x = *(uint32_t*)&a;
    r.y = *(uint32_t*)&b;
    o[i] = r;
}

// ---------------- pre-pass: W [E][K][N] fp32 -> Wt [E][N][K] fp16 ----------------
__device__ __forceinline__ void tr_w_body(const float* __restrict__ W, __half* __restrict__ Wt,
                                          int K, int N, int e) {
    __shared__ float s[64][65];
    const int n0 = blockIdx.x * 64;
    const int k0 = blockIdx.y * 64;
    const float* We = W + (size_t)e * K * N;
    __half* Wte = Wt + (size_t)e * K * N;
    const int tx = threadIdx.x & 63, ty = threadIdx.x >> 6;
    #pragma unroll
    for (int r = 0; r < 16; r++)
        s[ty * 16 + r][tx] = We[(size_t)(k0 + ty * 16 + r) * N + n0 + tx];
    __syncthreads();
    #pragma unroll
    for (int r = 0; r < 16; r++)
        Wte[(size_t)(n0 + ty * 16 + r) * K + k0 + tx] = __float2half_rn(s[tx][ty * 16 + r]);
}

__global__ void __launch_bounds__(256) tr_w(const float* __restrict__ W, __half* __restrict__ Wt,
                                            int K, int N) {
    tr_w_body(W, Wt, K, N, blockIdx.z);
}

// batched gate+down transpose: z in [0,16) -> gate for z<8, down for z>=8
__global__ void __launch_bounds__(256) tr_w_gd(const float* __restrict__ gate,
                                               const float* __restrict__ down) {
    const int z = blockIdx.z;
    if (z < NE) tr_w_body(gate, g_gt, NDIN, NDH, z);
    else        tr_w_body(down, g_dt, NDIN, NDH, z - NE);
}

// ---------------- fused GEMM1+2: h = silu(x@gate^T) * (x@down^T) ----------------
// NEW: BM=128, BN=64, BK=64. 3-stage x 32KB = 96KB -> 2 CTA/SM.
// 256 threads = 8 warps (4m x 2n), warp tile 32x32, dual accumulators.
__global__ void __launch_bounds__(256, 2)
gemm_fused(const __half* __restrict__ A, const __half* __restrict__ Bg,
           const __half* __restrict__ Bd, __half* __restrict__ H, int N, int K)
{
    extern __shared__ char sm[];
    const uint32_t sbase = smem_u32(sm);
    const int NK = K >> 6;                 // 32
    const int e = blockIdx.z, bm = blockIdx.y * 128, bn = blockIdx.x * 64;
    const int tid = threadIdx.x, lane = tid & 31, wid = tid >> 5;

    const char* Ae  = (const char*)(A  + ((size_t)e * NT + bm) * K);
    const char* Bge = (const char*)(Bg + ((size_t)e * N  + bn) * K);
    const char* Bde = (const char*)(Bd + ((size_t)e * N  + bn) * K);
    const size_t rowstride = (size_t)K * 2;

    // stage layout: A 16KB | Bg 8KB | Bd 8KB = 32KB
    auto stage_load = [&](int kc, int s) {
        if (kc < NK) {
            const uint32_t d = sbase + (uint32_t)s * 32768u;
            const char* pa = Ae  + (size_t)kc * 128;
            const char* pg = Bge + (size_t)kc * 128;
            const char* pd = Bde + (size_t)kc * 128;
            // A: 128 rows x 8 chunks of 16B
            #pragma unroll
            for (int i = 0; i < 4; i++) {
                const int r = i * 32 + (tid >> 3);
                const int c = tid & 7;
                const uint32_t sw = (uint32_t)r * 128 + (uint32_t)((c ^ (r & 7)) << 4);
                CP16(d + sw, pa + (size_t)r * rowstride + c * 16);
            }
            // Bg/Bd: 64 rows x 8 chunks each
            #pragma unroll
            for (int i = 0; i < 2; i++) {
                const int r = i * 32 + (tid >> 3);
                const int c = tid & 7;
                const uint32_t sw = (uint32_t)r * 128 + (uint32_t)((c ^ (r & 7)) << 4);
                const size_t go = (size_t)r * rowstride + c * 16;
                CP16(d + 16384u + sw, pg + go);
                CP16(d + 24576u + sw, pd + go);
            }
        }
        CP_COMMIT();
    };

    stage_load(0, 0);
    stage_load(1, 1);

    const int wm = (wid >> 1) * 32;        // 4 warps along m
    const int wn = (wid & 1) * 32;         // 2 warps along n
    const int grp = lane >> 2, tig = lane & 3;
    const int hiA = lane >> 4;
    const int hiB = (lane >> 3) & 1;
    const int s7  = lane & 7;
    const int nrow = (lane & 7) + ((lane >> 4) << 3);   // B x4 row pattern

    float ag[2][4][4], ad_[2][4][4];
    #pragma unroll
    for (int i = 0; i < 2; i++)
        #pragma unroll
        for (int j = 0; j < 4; j++)
            #pragma unroll
            for (int q = 0; q < 4; q++) { ag[i][j][q] = 0.0f; ad_[i][j][q] = 0.0f; }

    for (int kc = 0; kc < NK; kc++) {
        const int s = kc % 3;
        CP_WAITG(1);
        __syncthreads();
        // refill stage consumed last iteration
        stage_load(kc + 2, (kc + 2) % 3);

        const uint32_t sA  = sbase + (uint32_t)s * 32768u;
        const uint32_t aBase  = sA + (uint32_t)(wm + (lane & 15)) * 128;
        const uint32_t bgBase = sA + 16384u + (uint32_t)(wn + nrow) * 128;
        const uint32_t bdBase = sA + 24576u + (uint32_t)(wn + nrow) * 128;

        #pragma unroll
        for (int ks = 0; ks < 4; ks++) {
            uint32_t af[2][4], bg[2][4], bd[2][4];
            const uint32_t ca = (uint32_t)(((ks * 2 + hiA) ^ s7) << 4);
            const uint32_t cb = (uint32_t)(((ks * 2 + hiB) ^ s7) << 4);
            #pragma unroll
            for (int mt = 0; mt < 2; mt++)
                LDSM_X4(af[mt], aBase + (uint32_t)mt * 2048 + ca);
            #pragma unroll
            for (int n4 = 0; n4 < 2; n4++) {
                LDSM_X4(bg[n4], bgBase + (uint32_t)n4 * 2048 + cb);
                LDSM_X4(bd[n4], bdBase + (uint32_t)n4 * 2048 + cb);
            }
            #pragma unroll
            for (int mt = 0; mt < 2; mt++)
                #pragma unroll
                for (int nt = 0; nt < 4; nt++) {
                    HMMA(ag[mt][nt],  af[mt], &bg[nt >> 1][(nt & 1) * 2]);
                    HMMA(ad_[mt][nt], af[mt], &bd[nt >> 1][(nt & 1) * 2]);
                }
        }
    }

    // epilogue: h = silu(g) * d, fp16
    #pragma unroll
    for (int mt = 0; mt < 2; mt++) {
        #pragma unroll
        for (int nt = 0; nt < 4; nt++) {
            const int row0 = bm + wm + mt * 16 + grp;
            const int col0 = bn + wn + nt * 8 + tig * 2;
            float h0 = silu(ag[mt][nt][0]) * ad_[mt][nt][0];
            float h1 = silu(ag[mt][nt][1]) * ad_[mt][nt][1];
            float h2 = silu(ag[mt][nt][2]) * ad_[mt][nt][2];
            float h3 = silu(ag[mt][nt][3]) * ad_[mt][nt][3];
            __half* out = H + ((size_t)e * NT + row0) * N + col0;
            *(__half2*)out = __floats2half2_rn(h0, h1);
            *(__half2*)(out + (size_t)8 * N) = __floats2half2_rn(h2, h3);
        }
    }
}

// ---------------- GEMM3: out = h @ up^T (fp32 out) ----------------
// R12 config: BM=BN=128, BK=64, 3-stage (prefetch 2, waitg 1), single barrier,
// 256 threads = 8 warps (2m x 4n), warp tile 64x32, 2 CTA/SM.
__global__ void __launch_bounds__(256, 2)
gemm_hmma(const __half* __restrict__ A, const __half* __restrict__ Bt,
          float* __restrict__ Cout, int N, int K)
{
    extern __shared__ char sm[];
    const uint32_t sbase = smem_u32(sm);
    const int NK = K >> 6;
    const int e = blockIdx.z, bm = blockIdx.y * 128, bn = blockIdx.x * 128;
    const int tid = threadIdx.x, lane = tid & 31, wid = tid >> 5;

    const char* Ae = (const char*)(A  + ((size_t)e * NT + bm) * K);
    const char* Be = (const char*)(Bt + ((size_t)e * N  + bn) * K);
    const size_t rowstride = (size_t)K * 2;

    auto stage_load = [&](int kc, int s) {
        if (kc < NK) {
            const uint32_t dA = sbase + s * 32768u;
            const uint32_t dB = dA + 16384u;
            const char* pa = Ae + (size_t)kc * 128;
            const char* pb = Be + (size_t)kc * 128;
            #pragma unroll
            for (int i = 0; i < 4; i++) {
                const int r = i * 32 + (tid >> 3);
                const int c = tid & 7;
                const uint32_t sw = (uint32_t)r * 128 + (uint32_t)((c ^ (r & 7)) << 4);
                const size_t go = (size_t)r * rowstride + c * 16;
                CP16(dA + sw, pa + go);
                CP16(dB + sw, pb + go);
            }
        }
        CP_COMMIT();
    };

    stage_load(0, 0);
    stage_load(1, 1);

    const int wm = (wid >> 2) * 64;
    const int wn = (wid & 3) * 32;
    const int grp = lane >> 2, tig = lane & 3;
    const int hiA = lane >> 4;
    const int hiB = (lane >> 3) & 1;
    const int s7  = lane & 7;

    float acc[4][4][4];
    #pragma unroll
    for (int i = 0; i < 4; i++)
        #pragma unroll
        for (int j = 0; j < 4; j++)
            #pragma unroll
            for (int q = 0; q < 4; q++)
                acc[i][j][q] = 0.0f;

    for (int kc = 0; kc < NK; kc++) {
        const int s = kc % 3;
        CP_WAITG(1);
        __syncthreads();
        // refill stage consumed last iteration
        stage_load(kc + 2, (kc + 2) % 3);

        const uint32_t sA = sbase + s * 32768u;
        const uint32_t sB = sA + 16384u;
        const uint32_t aBase = sA + (uint32_t)(wm + (lane & 15)) * 128;
        const uint32_t bBase = sB + (uint32_t)(wn + (lane & 7)) * 128;

        #pragma unroll
        for (int ks = 0; ks < 4; ks++) {
            uint32_t af[4][4], bf[4][2];
            const uint32_t ca = (uint32_t)(((ks * 2 + hiA) ^ s7) << 4);
            const uint32_t cb = (uint32_t)(((ks * 2 + hiB) ^ s7) << 4);
            #pragma unroll
            for (int mt = 0; mt < 4; mt++)
                LDSM_X4(af[mt], aBase + (uint32_t)mt * 2048 + ca);
            #pragma unroll
            for (int nt = 0; nt < 4; nt++)
                LDSM_X2(bf[nt], bBase + (uint32_t)nt * 1024 + cb);
            #pragma unroll
            for (int mt = 0; mt < 4; mt++)
                #pragma unroll
                for (int nt = 0; nt < 4; nt++)
                    HMMA(acc[mt][nt], af[mt], bf[nt]);
        }
    }

    #pragma unroll
    for (int mt = 0; mt < 4; mt++) {
        #pragma unroll
        for (int nt = 0; nt < 4; nt++) {
            const int row0 = bm + wm + mt * 16 + grp;
            const int col0 = bn + wn + nt * 8 + tig * 2;
            float* out = Cout + ((size_t)e * NT + row0) * N + col0;
            *(float2*)out = make_float2(acc[mt][nt][0], acc[mt][nt][1]);
            *(float2*)(out + (size_t)8 * N) = make_float2(acc[mt][nt][2], acc[mt][nt][3]);
        }
    }
}

// ---------------- host ----------------
extern "C" void kernel_launch(void* const* d_in, const int* in_sizes, int n_in,
                              void* d_out, int out_size) {
    const float* x    = (const float*)d_in[0];
    const float* gate = (const float*)d_in[1];
    const float* down = (const float*)d_in[2];
    const float* up   = (const float*)d_in[3];
    float* out = (float*)d_out;

    void *xh, *gt, *dt, *ut, *hp;
    cudaGetSymbolAddress(&xh, g_xh);
    cudaGetSymbolAddress(&gt, g_gt);
    cudaGetSymbolAddress(&dt, g_dt);
    cudaGetSymbolAddress(&ut, g_ut);
    cudaGetSymbolAddress(&hp, g_h);

    const int SMEM_F = 3 * 32768;   // 96 KB (2 CTA/SM)
    const int SMEM_3 = 3 * 32768;   // 96 KB
    cudaFuncSetAttribute(gemm_fused, cudaFuncAttributeMaxDynamicSharedMemorySize, SMEM_F);
    cudaFuncSetAttribute(gemm_hmma,  cudaFuncAttributeMaxDynamicSharedMemorySize, SMEM_3);

    // fork/join: overlap weight transposes (side stream) with cvt_x and gemm_fused
    cudaStream_t side;
    cudaStreamCreateWithFlags(&side, cudaStreamNonBlocking);
    cudaEvent_t e0, e1, e2;
    cudaEventCreateWithFlags(&e0, cudaEventDisableTiming);
    cudaEventCreateWithFlags(&e1, cudaEventDisableTiming);
    cudaEventCreateWithFlags(&e2, cudaEventDisableTiming);

    cudaEventRecord(e0, 0);
    cudaStreamWaitEvent(side, e0, 0);

    // side stream: gate+down transpose, then up transpose
    tr_w_gd<<<dim3(NDH / 64, NDIN / 64, 2 * NE), 256, 0, side>>>(gate, down);
    cudaEventRecord(e1, side);
    tr_w<<<dim3(NDIN / 64, NDH / 64, NE), 256, 0, side>>>(up, (__half*)ut, NDH, NDIN);
    cudaEventRecord(e2, side);

    // main stream: x conversion (concurrent with tr_w_gd)
    cvt_x<<<(NE * NT * NDIN / 4) / 256, 256>>>((const float4*)x, (uint2*)xh);

    // fused needs gate^T/down^T
    cudaStreamWaitEvent(0, e1, 0);
    gemm_fused<<<dim3(NDH / 64, NT / 128, NE), 256, SMEM_F>>>(
        (const __half*)xh, (const __half*)gt, (const __half*)dt, (__half*)hp, NDH, NDIN);

    // GEMM3 needs up^T (tr_w(up) overlapped with gemm_fused)
    cudaStreamWaitEvent(0, e2, 0);
    gemm_hmma<<<dim3(NDIN / 128, NT / 128, NE), 256, SMEM_3>>>(
        (const __half*)hp, (const __half*)ut, out, NDIN, NDH);

    cudaEventDestroy(e0);
    cudaEventDestroy(e1);
    cudaEventDestroy(e2);
    cudaStreamDestroy(side);
}